// round 12
// baseline (speedup 1.0000x reference)
#include <cuda_runtime.h>
#include <cstdint>

#define BB 8
#define NN 8192
#define MM 2048
#define NUM_ITER 4
#define BASE_ALPHA 0.1f

// Scratch: nearest point (xyz) + min_dist per (b,n); per-iter per-batch max bits.
__device__ float4 g_near[BB * NN];
__device__ int    g_maxbits[NUM_ITER * BB];

// ---------------------------------------------------------------------------
// f32x2 packed helpers (Blackwell FFMA2 path, PTX fma.rn.f32x2)
// ---------------------------------------------------------------------------
__device__ __forceinline__ uint64_t pack2(float lo, float hi) {
    uint64_t r;
    asm("mov.b64 %0, {%1, %2};" : "=l"(r) : "f"(lo), "f"(hi));
    return r;
}
__device__ __forceinline__ uint64_t ffma2(uint64_t a, uint64_t b, uint64_t c) {
    uint64_t d;
    asm("fma.rn.f32x2 %0, %1, %2, %3;" : "=l"(d) : "l"(a), "l"(b), "l"(c));
    return d;
}
__device__ __forceinline__ void unpack2(uint64_t v, float& lo, float& hi) {
    asm("mov.b64 {%0, %1}, %2;" : "=f"(lo), "=f"(hi) : "l"(v));
}

// ---------------------------------------------------------------------------
// Init: copy pred -> out, zero max slots.
// ---------------------------------------------------------------------------
__global__ void ipgr_init_kernel(const float4* __restrict__ pred,
                                 float4* __restrict__ out) {
    int i = blockIdx.x * blockDim.x + threadIdx.x;
    if (i < NUM_ITER * BB) g_maxbits[i] = 0;
    const int total4 = BB * NN * 3 / 4;  // 49152 float4
    for (; i < total4; i += gridDim.x * blockDim.x) out[i] = pred[i];
}

// ---------------------------------------------------------------------------
// NN search with fused application of previous iteration's blend (iter>=1).
// Identical to the R11 kernel EXCEPT the k-loop is software-pipelined:
// the next iteration's 4 smem vectors are loaded before the current
// iteration's math, hiding the ~29-cycle LDS latency behind ~54 independent
// ops (every k-step previously began with a long_scoreboard stall on vx).
// sm[] is padded by 16 floats so the final prefetch (k=127 -> vector 512+q)
// stays in-bounds; its data is discarded.
// block = 128 threads (4 warps), grid = (NN/128, BB) = (64, 8) = 512 blocks.
// Lane layout: q = lane>>3 (M-slice), sub = lane&7; 4 points per thread.
// Conflict-free slice interleave: slice q owns 16B vectors v = 4k + q.
// Argmin: value-only quad tournament (3 FMNMX) tracking vector counter k
// (strict < keeps earliest k = smallest m in slice); position within the
// winning vector recovered post-loop by bit-exact scalar recomputation,
// scanning positions 3..0 -> exact first-index tie-break. Cross-slice/lane
// merges compare (value, then m).
// Comparison key: t = |y|^2/2 - x.y (argmin-equivalent; |x|^2 const/point).
// ---------------------------------------------------------------------------
__global__ void __launch_bounds__(128, 4)
ipgr_nn_kernel(float* __restrict__ refined,
               const float* __restrict__ partial,
               int iter) {
    // SoA tile: yx | yy | yz | yh(=0.5*|y|^2), each MM floats, +16 pad for
    // the k=127 prefetch overrun.
    __shared__ __align__(16) float sm[4 * MM + 16];
    __shared__ float smax[4];

    const int b = blockIdx.y;
    const float* p = partial + (size_t)b * MM * 3;

    for (int m = threadIdx.x; m < MM; m += 128) {
        float yx = p[m * 3 + 0];
        float yy = p[m * 3 + 1];
        float yz = p[m * 3 + 2];
        sm[m]          = yx;
        sm[MM + m]     = yy;
        sm[2 * MM + m] = yz;
        sm[3 * MM + m] = 0.5f * fmaf(yz, yz, fmaf(yy, yy, yx * yx));
    }
    __syncthreads();

    const int lane = threadIdx.x & 31;
    const int warp = threadIdx.x >> 5;
    const int q    = lane >> 3;        // 4 interleaved M-slices
    const int sub  = lane & 7;
    const int n0   = blockIdx.x * 128 + warp * 32 + sub * 4;  // 4 points/thread

    // Prologue: load 4 pred points; iter>0 applies previous blend inline
    // (per-batch max complete at kernel boundary). All q-lanes compute the
    // identical update; q==0 stores back (warp-exclusive point ownership).
    uint64_t xp0[4], xp1[4], xp2[4];  // packed (-x, -x)
    float xs[4];
    {
        float* rp = refined + ((size_t)b * NN + n0) * 3;
        float mxp = 1.0f;
        if (iter > 0)
            mxp = __int_as_float(g_maxbits[(iter - 1) * BB + b]) + 1e-6f;
#pragma unroll
        for (int i = 0; i < 4; i++) {
            float x0 = rp[i * 3 + 0];
            float x1 = rp[i * 3 + 1];
            float x2 = rp[i * 3 + 2];
            if (iter > 0) {
                float4 nd = g_near[b * NN + n0 + i];
                float alpha = BASE_ALPHA * (2.0f - nd.w / mxp);
                x0 = fmaf(alpha, nd.x - x0, x0);
                x1 = fmaf(alpha, nd.y - x1, x1);
                x2 = fmaf(alpha, nd.z - x2, x2);
                if (q == 0) {
                    rp[i * 3 + 0] = x0;
                    rp[i * 3 + 1] = x1;
                    rp[i * 3 + 2] = x2;
                }
            }
            xp0[i] = pack2(-x0, -x0);
            xp1[i] = pack2(-x1, -x1);
            xp2[i] = pack2(-x2, -x2);
            xs[i]  = fmaf(x2, x2, fmaf(x1, x1, x0 * x0));
        }
    }

    // One accumulator per point: best quad-min value + vector counter k.
    float best[4] = {3.4e38f, 3.4e38f, 3.4e38f, 3.4e38f};
    int   bk[4]   = {0, 0, 0, 0};

    // Interleaved: slice q reads vector 4k + q of each component array.
    const ulonglong2* pyx = reinterpret_cast<const ulonglong2*>(sm)          + q;
    const ulonglong2* pyy = reinterpret_cast<const ulonglong2*>(sm + MM)     + q;
    const ulonglong2* pyz = reinterpret_cast<const ulonglong2*>(sm + 2 * MM) + q;
    const ulonglong2* pyh = reinterpret_cast<const ulonglong2*>(sm + 3 * MM) + q;

    // Software pipeline: prefetch k+1's vectors before k's tournament.
    ulonglong2 vx = pyx[0];
    ulonglong2 vy = pyy[0];
    ulonglong2 vz = pyz[0];
    ulonglong2 vh = pyh[0];

#pragma unroll 4
    for (int k = 0; k < 128; k++) {
        // Prefetch next (k=127 reads padded garbage, discarded).
        ulonglong2 nvx = pyx[4 * (k + 1)];
        ulonglong2 nvy = pyy[4 * (k + 1)];
        ulonglong2 nvz = pyz[4 * (k + 1)];
        ulonglong2 nvh = pyh[4 * (k + 1)];
#pragma unroll
        for (int i = 0; i < 4; i++) {
            uint64_t t01 = ffma2(xp0[i], vx.x, vh.x);
            t01 = ffma2(xp1[i], vy.x, t01);
            t01 = ffma2(xp2[i], vz.x, t01);
            uint64_t t23 = ffma2(xp0[i], vx.y, vh.y);
            t23 = ffma2(xp1[i], vy.y, t23);
            t23 = ffma2(xp2[i], vz.y, t23);
            float t0, t1, t2, t3;
            unpack2(t01, t0, t1);
            unpack2(t23, t2, t3);
            float qmin = fminf(fminf(t0, t1), fminf(t2, t3));  // 3 FMNMX
            bool c = qmin < best[i];   // strict: earliest k = smallest m kept
            best[i] = c ? qmin : best[i];
            bk[i]   = c ? k    : bk[i];
        }
        vx = nvx; vy = nvy; vz = nvz; vh = nvh;
    }

    // Recover position within each point's winning vector by bit-exact
    // scalar recomputation (same fma order/rounding as the f32x2 lanes).
    // Scan 3..0 so the smallest matching position survives.
    float bv[4];
    int   bm[4];
#pragma unroll
    for (int i = 0; i < 4; i++) {
        float nx0, nx1, nx2, du;
        unpack2(xp0[i], nx0, du);
        unpack2(xp1[i], nx1, du);
        unpack2(xp2[i], nx2, du);
        const int m0 = (4 * bk[i] + q) * 4;  // first m of winning vector
        int pos = 3;
#pragma unroll
        for (int j = 2; j >= 0; j--) {
            int mj = m0 + j;
            float tj = fmaf(nx2, sm[2 * MM + mj],
                       fmaf(nx1, sm[MM + mj],
                       fmaf(nx0, sm[mj], sm[3 * MM + mj])));
            if (tj == best[i]) pos = j;
        }
        bv[i] = best[i];
        bm[i] = m0 + pos;
    }

    // Merge the 4 M-slices across lanes (bits 3,4). Tie -> smaller m.
#pragma unroll
    for (int r = 8; r <= 16; r <<= 1) {
#pragma unroll
        for (int i = 0; i < 4; i++) {
            float ob = __shfl_xor_sync(0xffffffffu, bv[i], r);
            int   oi = __shfl_xor_sync(0xffffffffu, bm[i], r);
            if (ob < bv[i] || (ob == bv[i] && oi < bm[i])) { bv[i] = ob; bm[i] = oi; }
        }
    }

    // Lanes with q==0 hold final results; write nearest + min_dist.
    float mloc = 0.0f;
    if (q == 0) {
#pragma unroll
        for (int i = 0; i < 4; i++) {
            int mi = bm[i];
            float d2 = fmaf(2.0f, bv[i], xs[i]);
            float md = sqrtf(fmaxf(d2, 0.0f));
            g_near[b * NN + n0 + i] =
                make_float4(sm[mi], sm[MM + mi], sm[2 * MM + mi], md);
            mloc = fmaxf(mloc, md);
        }
    }

    // Warp max, then block max via smem, one atomic per block.
#pragma unroll
    for (int o = 16; o > 0; o >>= 1)
        mloc = fmaxf(mloc, __shfl_xor_sync(0xffffffffu, mloc, o));
    if (lane == 0) smax[warp] = mloc;
    __syncthreads();
    if (threadIdx.x == 0) {
        float m01 = fmaxf(smax[0], smax[1]);
        float m23 = fmaxf(smax[2], smax[3]);
        atomicMax(&g_maxbits[iter * BB + b],
                  __float_as_int(fmaxf(m01, m23)));
    }
}

// ---------------------------------------------------------------------------
// Final blend (applies the last iteration's update).
// ---------------------------------------------------------------------------
__global__ void ipgr_update_kernel(float* __restrict__ refined, int iter) {
    const int gi = blockIdx.x * blockDim.x + threadIdx.x;  // b*NN + n
    const int b  = gi >> 13;  // NN = 8192

    float4 nd = g_near[gi];
    float  mx = __int_as_float(g_maxbits[iter * BB + b]);
    float  alpha = BASE_ALPHA * (2.0f - nd.w / (mx + 1e-6f));

    float r0 = refined[gi * 3 + 0];
    float r1 = refined[gi * 3 + 1];
    float r2 = refined[gi * 3 + 2];
    refined[gi * 3 + 0] = fmaf(alpha, nd.x - r0, r0);
    refined[gi * 3 + 1] = fmaf(alpha, nd.y - r1, r1);
    refined[gi * 3 + 2] = fmaf(alpha, nd.z - r2, r2);
}

// ---------------------------------------------------------------------------
extern "C" void kernel_launch(void* const* d_in, const int* in_sizes, int n_in,
                              void* d_out, int out_size) {
    const float* pred    = (const float*)d_in[0];  // [8, 8192, 3] f32
    const float* partial = (const float*)d_in[1];  // [8, 2048, 3] f32
    float* out = (float*)d_out;                     // [8, 8192, 3] f32

    (void)in_sizes; (void)n_in; (void)out_size;

    ipgr_init_kernel<<<192, 256>>>((const float4*)pred, (float4*)out);

    dim3 gridA(NN / 128, BB);  // (64, 8) = 512 blocks
    for (int it = 0; it < NUM_ITER; it++)
        ipgr_nn_kernel<<<gridA, 128>>>(out, partial, it);

    ipgr_update_kernel<<<(BB * NN) / 256, 256>>>(out, NUM_ITER - 1);
}

// round 13
// speedup vs baseline: 1.1210x; 1.1210x over previous
#include <cuda_runtime.h>
#include <cstdint>

#define BB 8
#define NN 8192
#define MM 2048
#define NUM_ITER 4
#define BASE_ALPHA 0.1f
#define BLOCKS_PER_BATCH 64   // NN/128

// Per-iter per-batch max bits + per-iter per-batch arrival counters.
__device__ int g_maxbits[NUM_ITER * BB];
__device__ int g_arrive [NUM_ITER * BB];

// ---------------------------------------------------------------------------
// f32x2 packed helpers (Blackwell FFMA2 path, PTX fma.rn.f32x2)
// ---------------------------------------------------------------------------
__device__ __forceinline__ uint64_t pack2(float lo, float hi) {
    uint64_t r;
    asm("mov.b64 %0, {%1, %2};" : "=l"(r) : "f"(lo), "f"(hi));
    return r;
}
__device__ __forceinline__ uint64_t ffma2(uint64_t a, uint64_t b, uint64_t c) {
    uint64_t d;
    asm("fma.rn.f32x2 %0, %1, %2, %3;" : "=l"(d) : "l"(a), "l"(b), "l"(c));
    return d;
}
__device__ __forceinline__ void unpack2(uint64_t v, float& lo, float& hi) {
    asm("mov.b64 {%0, %1}, %2;" : "=f"(lo), "=f"(hi) : "l"(v));
}

// ---------------------------------------------------------------------------
// Init: zero the max slots and barrier counters (runs before the persistent
// kernel every replay; ordering via stream dependency).
// ---------------------------------------------------------------------------
__global__ void ipgr_init_kernel() {
    int i = threadIdx.x;
    if (i < NUM_ITER * BB) {
        g_maxbits[i] = 0;
        g_arrive[i]  = 0;
    }
}

// ---------------------------------------------------------------------------
// Persistent NN + refine kernel: all NUM_ITER iterations in one launch.
// block = 128 threads (4 warps), grid = (NN/128, BB) = (64, 8) = 512 blocks.
// All 512 blocks are co-resident (smem 33KB -> 6 blocks/SM; 148*6=888>=512),
// so the per-batch software barrier (64 blocks arrive on g_arrive[it*BB+b],
// spin on volatile read) cannot deadlock.
// Points live in registers across iterations: after the shfl butterfly every
// lane holds the merged (value, m) for its 4 points, so the blend update is
// register-local. Only the per-batch max crosses blocks (atomicMax -> fence
// -> arrive -> spin -> __ldcg). Final refined written to gmem once.
// Inner loop identical to the best-measured R11 kernel:
//   q = lane>>3 selects one of 4 interleaved M-slices (vector v = 4k + q,
//   conflict-free LDS); value-only quad tournament (3 FMNMX) tracking vector
//   counter k (strict < keeps earliest k = smallest m in slice); position in
//   the winning vector recovered by bit-exact scalar recomputation (scan
//   3..0) -> exact first-index tie-break; merges compare (value, then m).
// Comparison key: t = |y|^2/2 - x.y (argmin-equivalent; |x|^2 const/point).
// ---------------------------------------------------------------------------
__global__ void __launch_bounds__(128)
ipgr_persist_kernel(const float* __restrict__ pred,
                    const float* __restrict__ partial,
                    float* __restrict__ out) {
    // SoA tile of partial: yx | yy | yz | yh(=0.5*|y|^2), each MM floats.
    __shared__ __align__(16) float sm[4 * MM];
    __shared__ float smax[4];
    __shared__ float s_mx;

    const int b = blockIdx.y;
    const float* p = partial + (size_t)b * MM * 3;

    for (int m = threadIdx.x; m < MM; m += 128) {
        float yx = p[m * 3 + 0];
        float yy = p[m * 3 + 1];
        float yz = p[m * 3 + 2];
        sm[m]          = yx;
        sm[MM + m]     = yy;
        sm[2 * MM + m] = yz;
        sm[3 * MM + m] = 0.5f * fmaf(yz, yz, fmaf(yy, yy, yx * yx));
    }

    const int lane = threadIdx.x & 31;
    const int warp = threadIdx.x >> 5;
    const int q    = lane >> 3;        // 4 interleaved M-slices
    const int sub  = lane & 7;
    const int n0   = blockIdx.x * 128 + warp * 32 + sub * 4;  // 4 points/thread

    // Load the 4 pred points into registers (refined state lives here).
    float x0[4], x1[4], x2[4];
    {
        const float* rp = pred + ((size_t)b * NN + n0) * 3;
#pragma unroll
        for (int i = 0; i < 4; i++) {
            x0[i] = rp[i * 3 + 0];
            x1[i] = rp[i * 3 + 1];
            x2[i] = rp[i * 3 + 2];
        }
    }
    __syncthreads();

    const ulonglong2* pyx = reinterpret_cast<const ulonglong2*>(sm)          + q;
    const ulonglong2* pyy = reinterpret_cast<const ulonglong2*>(sm + MM)     + q;
    const ulonglong2* pyz = reinterpret_cast<const ulonglong2*>(sm + 2 * MM) + q;
    const ulonglong2* pyh = reinterpret_cast<const ulonglong2*>(sm + 3 * MM) + q;

    for (int it = 0; it < NUM_ITER; it++) {
        // Pack negated coords for FFMA2; |x|^2 per point.
        uint64_t xp0[4], xp1[4], xp2[4];
        float xs[4];
#pragma unroll
        for (int i = 0; i < 4; i++) {
            xp0[i] = pack2(-x0[i], -x0[i]);
            xp1[i] = pack2(-x1[i], -x1[i]);
            xp2[i] = pack2(-x2[i], -x2[i]);
            xs[i]  = fmaf(x2[i], x2[i], fmaf(x1[i], x1[i], x0[i] * x0[i]));
        }

        float best[4] = {3.4e38f, 3.4e38f, 3.4e38f, 3.4e38f};
        int   bk[4]   = {0, 0, 0, 0};

#pragma unroll 2
        for (int k = 0; k < 128; k++) {
            ulonglong2 vx = pyx[4 * k];
            ulonglong2 vy = pyy[4 * k];
            ulonglong2 vz = pyz[4 * k];
            ulonglong2 vh = pyh[4 * k];
#pragma unroll
            for (int i = 0; i < 4; i++) {
                uint64_t t01 = ffma2(xp0[i], vx.x, vh.x);
                t01 = ffma2(xp1[i], vy.x, t01);
                t01 = ffma2(xp2[i], vz.x, t01);
                uint64_t t23 = ffma2(xp0[i], vx.y, vh.y);
                t23 = ffma2(xp1[i], vy.y, t23);
                t23 = ffma2(xp2[i], vz.y, t23);
                float t0, t1, t2, t3;
                unpack2(t01, t0, t1);
                unpack2(t23, t2, t3);
                float qmin = fminf(fminf(t0, t1), fminf(t2, t3));
                bool c = qmin < best[i];   // strict: earliest k kept
                best[i] = c ? qmin : best[i];
                bk[i]   = c ? k    : bk[i];
            }
        }

        // Recover exact position (bit-exact scalar recompute, scan 3..0).
        float bv[4];
        int   bm[4];
#pragma unroll
        for (int i = 0; i < 4; i++) {
            const int m0 = (4 * bk[i] + q) * 4;
            int pos = 3;
#pragma unroll
            for (int j = 2; j >= 0; j--) {
                int mj = m0 + j;
                float tj = fmaf(-x2[i], sm[2 * MM + mj],
                           fmaf(-x1[i], sm[MM + mj],
                           fmaf(-x0[i], sm[mj], sm[3 * MM + mj])));
                if (tj == best[i]) pos = j;
            }
            bv[i] = best[i];
            bm[i] = m0 + pos;
        }

        // Butterfly merge across the 4 slices: ALL lanes end with the merged
        // (value, m) for their shared 4 points. Tie -> smaller m.
#pragma unroll
        for (int r = 8; r <= 16; r <<= 1) {
#pragma unroll
            for (int i = 0; i < 4; i++) {
                float ob = __shfl_xor_sync(0xffffffffu, bv[i], r);
                int   oi = __shfl_xor_sync(0xffffffffu, bm[i], r);
                if (ob < bv[i] || (ob == bv[i] && oi < bm[i])) { bv[i] = ob; bm[i] = oi; }
            }
        }

        // min_dist per point (every lane computes; identical across q-lanes).
        float md[4];
        float mloc = 0.0f;
#pragma unroll
        for (int i = 0; i < 4; i++) {
            float d2 = fmaf(2.0f, bv[i], xs[i]);
            md[i] = sqrtf(fmaxf(d2, 0.0f));
            mloc = fmaxf(mloc, md[i]);
        }

        // Block max -> one atomicMax per block (md >= 0: int order == float).
#pragma unroll
        for (int o = 16; o > 0; o >>= 1)
            mloc = fmaxf(mloc, __shfl_xor_sync(0xffffffffu, mloc, o));
        if (lane == 0) smax[warp] = mloc;
        __syncthreads();

        const int slot = it * BB + b;
        if (threadIdx.x == 0) {
            float m01 = fmaxf(smax[0], smax[1]);
            float m23 = fmaxf(smax[2], smax[3]);
            atomicMax(&g_maxbits[slot], __float_as_int(fmaxf(m01, m23)));
            __threadfence();  // publish max before arrival
            atomicAdd(&g_arrive[slot], 1);
            // Spin until all 64 blocks of this batch arrived.
            while (*(volatile int*)&g_arrive[slot] < BLOCKS_PER_BATCH) { }
            __threadfence();
            s_mx = __int_as_float(__ldcg(&g_maxbits[slot]));
        }
        __syncthreads();
        const float mxp = s_mx + 1e-6f;

        // Register-local blend update (all lanes, same result per point).
#pragma unroll
        for (int i = 0; i < 4; i++) {
            int mi = bm[i];
            float alpha = BASE_ALPHA * (2.0f - md[i] / mxp);
            x0[i] = fmaf(alpha, sm[mi]          - x0[i], x0[i]);
            x1[i] = fmaf(alpha, sm[MM + mi]     - x1[i], x1[i]);
            x2[i] = fmaf(alpha, sm[2 * MM + mi] - x2[i], x2[i]);
        }
    }

    // Final store (q==0 lanes own the write; values identical across q).
    if (q == 0) {
        float* rp = out + ((size_t)b * NN + n0) * 3;
#pragma unroll
        for (int i = 0; i < 4; i++) {
            rp[i * 3 + 0] = x0[i];
            rp[i * 3 + 1] = x1[i];
            rp[i * 3 + 2] = x2[i];
        }
    }
}

// ---------------------------------------------------------------------------
extern "C" void kernel_launch(void* const* d_in, const int* in_sizes, int n_in,
                              void* d_out, int out_size) {
    const float* pred    = (const float*)d_in[0];  // [8, 8192, 3] f32
    const float* partial = (const float*)d_in[1];  // [8, 2048, 3] f32
    float* out = (float*)d_out;                     // [8, 8192, 3] f32

    (void)in_sizes; (void)n_in; (void)out_size;

    ipgr_init_kernel<<<1, 64>>>();

    dim3 grid(NN / 128, BB);  // (64, 8) = 512 blocks, all co-resident
    ipgr_persist_kernel<<<grid, 128>>>(pred, partial, out);
}